// round 6
// baseline (speedup 1.0000x reference)
#include <cuda_runtime.h>

#define TSEQ 512
#define INF  14
#define HID  8

typedef unsigned long long ull;

__device__ __forceinline__ ull pk(float lo, float hi){
    ull r; asm("mov.b64 %0, {%1,%2};" : "=l"(r) : "f"(lo), "f"(hi)); return r;
}
__device__ __forceinline__ float2 upk(ull v){
    float2 r; asm("mov.b64 {%0,%1}, %2;" : "=f"(r.x), "=f"(r.y) : "l"(v)); return r;
}
__device__ __forceinline__ ull ffma2(ull a, ull b, ull c){
    ull d; asm("fma.rn.f32x2 %0, %1, %2, %3;" : "=l"(d) : "l"(a), "l"(b), "l"(c)); return d;
}
__device__ __forceinline__ float tanhx(float x){
    float r; asm("tanh.approx.f32 %0, %1;" : "=f"(r) : "f"(x)); return r;
}
__device__ __forceinline__ float sigx(float x){
    return fmaf(0.5f, tanhx(0.5f * x), 0.5f);
}
// named barriers: F (h1 ready) ids 1,2 ; E (slot free) ids 3,4
__device__ __forceinline__ void bar_sync64(int id){
    asm volatile("bar.sync %0, 64;" :: "r"(id) : "memory");
}
__device__ __forceinline__ void bar_arrive64(int id){
    asm volatile("bar.arrive %0, 64;" :: "r"(id) : "memory");
}

// Block = 64 threads. warp0 = layer-1 engine, warp1 = layer-2 engine,
// both covering the SAME 4 batch elements (8 lanes each, lane owns h-index j).
// h1(t) handed off via double-buffered smem; warp1 runs one step behind warp0.
__global__ __launch_bounds__(64, 7) void lstm_forex_kernel(
    const float* __restrict__ x,
    const float* __restrict__ Wih1, const float* __restrict__ Whh1,
    const float* __restrict__ bih1, const float* __restrict__ bhh1,
    const float* __restrict__ Wih2, const float* __restrict__ Whh2,
    const float* __restrict__ bih2, const float* __restrict__ bhh2,
    const float* __restrict__ bn_gamma, const float* __restrict__ bn_beta,
    const float* __restrict__ bn_mean, const float* __restrict__ bn_var,
    const float* __restrict__ w1, const float* __restrict__ b1,
    const float* __restrict__ w2, const float* __restrict__ b2,
    float* __restrict__ out, int Bn)
{
    __shared__ __align__(16) float h1buf[2][32];   // [slot][grp*8 + j]
    __shared__ __align__(16) float h2buf[32];      // [grp*8 + j], warp1-private

    const int tid  = threadIdx.x;
    const int wid  = tid >> 5;
    const int lane = tid & 31;
    const int j    = lane & 7;
    const int grp  = lane >> 3;           // element within block (0..3)
    const int e    = blockIdx.x * 4 + grp;
    const bool valid = (e < Bn);
    const int ec = valid ? e : (Bn > 0 ? Bn - 1 : 0);
    const unsigned FULL = 0xffffffffu;

    if (wid == 0){
        // ================= Layer-1 producer warp =================
        ull wxp[4][7], wh1p[4][4], pb1[4];
#pragma unroll
        for (int g = 0; g < 4; g++){
            const int row = g * 8 + j;
#pragma unroll
            for (int k = 0; k < 7; k++)
                wxp[g][k] = pk(Wih1[row * 14 + 2*k], Wih1[row * 14 + 2*k + 1]);
#pragma unroll
            for (int k = 0; k < 4; k++)
                wh1p[g][k] = pk(Whh1[row * 8 + 2*k], Whh1[row * 8 + 2*k + 1]);
            pb1[g] = pk(bih1[row] + bhh1[row], 0.f);
        }
        const ull* px = reinterpret_cast<const ull*>(x) + (size_t)ec * (TSEQ * INF / 2);
        ull xb[7];
#pragma unroll
        for (int k = 0; k < 7; k++) xb[k] = px[k];
        px += 7;

        float c1;
        // ---- t = 0 : no recurrent term (h1(-1)=0) ----
        {
            ull a0 = pb1[0], a1 = pb1[1], a2 = pb1[2], a3 = pb1[3];
#pragma unroll
            for (int k = 0; k < 7; k++){
                a0 = ffma2(wxp[0][k], xb[k], a0);
                a1 = ffma2(wxp[1][k], xb[k], a1);
                a2 = ffma2(wxp[2][k], xb[k], a2);
                a3 = ffma2(wxp[3][k], xb[k], a3);
            }
            const float2 u0 = upk(a0), u2 = upk(a2), u3 = upk(a3);
            const float ai = sigx(u0.x + u0.y);
            const float ag = tanhx(u2.x + u2.y);
            const float ao = sigx(u3.x + u3.y);
            c1 = ai * ag;
            h1buf[0][grp * 8 + j] = ao * tanhx(c1);
        }
        __syncwarp(FULL);
        bar_arrive64(1);                  // F[0]
        // prefetch x(1)
#pragma unroll
        for (int k = 0; k < 7; k++) xb[k] = px[k];
        px += 7;

#pragma unroll 1
        for (int t = 1; t < TSEQ; t++){
            const int s = t & 1;
            // read h1(t-1) pairs from the other slot (broadcast LDS.128)
            const float* src = &h1buf[s ^ 1][grp * 8];
            const ulonglong2 va = *reinterpret_cast<const ulonglong2*>(src);
            const ulonglong2 vb = *reinterpret_cast<const ulonglong2*>(src + 4);
            ull a0 = pb1[0], a1 = pb1[1], a2 = pb1[2], a3 = pb1[3];
#pragma unroll
            for (int k = 0; k < 7; k++){
                a0 = ffma2(wxp[0][k], xb[k], a0);
                a1 = ffma2(wxp[1][k], xb[k], a1);
                a2 = ffma2(wxp[2][k], xb[k], a2);
                a3 = ffma2(wxp[3][k], xb[k], a3);
            }
            if (t + 1 < TSEQ){
#pragma unroll
                for (int k = 0; k < 7; k++) xb[k] = px[k];
                px += 7;
            }
            {
                const ull hp0 = va.x, hp1 = va.y, hp2 = vb.x, hp3 = vb.y;
                a0 = ffma2(wh1p[0][0], hp0, a0); a0 = ffma2(wh1p[0][1], hp1, a0);
                a0 = ffma2(wh1p[0][2], hp2, a0); a0 = ffma2(wh1p[0][3], hp3, a0);
                a1 = ffma2(wh1p[1][0], hp0, a1); a1 = ffma2(wh1p[1][1], hp1, a1);
                a1 = ffma2(wh1p[1][2], hp2, a1); a1 = ffma2(wh1p[1][3], hp3, a1);
                a2 = ffma2(wh1p[2][0], hp0, a2); a2 = ffma2(wh1p[2][1], hp1, a2);
                a2 = ffma2(wh1p[2][2], hp2, a2); a2 = ffma2(wh1p[2][3], hp3, a2);
                a3 = ffma2(wh1p[3][0], hp0, a3); a3 = ffma2(wh1p[3][1], hp1, a3);
                a3 = ffma2(wh1p[3][2], hp2, a3); a3 = ffma2(wh1p[3][3], hp3, a3);
            }
            const float2 u0 = upk(a0), u1 = upk(a1), u2 = upk(a2), u3 = upk(a3);
            const float ai = sigx(u0.x + u0.y);
            const float af = sigx(u1.x + u1.y);
            const float ag = tanhx(u2.x + u2.y);
            const float ao = sigx(u3.x + u3.y);
            c1 = fmaf(af, c1, ai * ag);
            const float h1n = ao * tanhx(c1);

            if (t >= 2) bar_sync64(3 + s);    // wait: consumer freed slot s
            h1buf[s][grp * 8 + j] = h1n;
            __syncwarp(FULL);
            bar_arrive64(1 + s);              // F[s]: h1(t) ready
        }
        // drain consumer's final E arrivals so barrier counts balance
        bar_sync64(3 + 0);
        bar_sync64(3 + 1);
    } else {
        // ================= Layer-2 consumer warp =================
        ull wi2p[4][4], wh2p[4][4], pb2[4];
#pragma unroll
        for (int g = 0; g < 4; g++){
            const int row = g * 8 + j;
#pragma unroll
            for (int k = 0; k < 4; k++){
                wi2p[g][k] = pk(Wih2[row * 8 + 2*k], Wih2[row * 8 + 2*k + 1]);
                wh2p[g][k] = pk(Whh2[row * 8 + 2*k], Whh2[row * 8 + 2*k + 1]);
            }
            pb2[g] = pk(bih2[row] + bhh2[row], 0.f);
        }
        h2buf[grp * 8 + j] = 0.f;         // h2(-1) = 0; ordered by first bar.sync(F)
        float h2 = 0.f, c2 = 0.f;

#pragma unroll 1
        for (int t = 0; t < TSEQ; t++){
            const int s = t & 1;
            bar_sync64(1 + s);            // wait h1(t)
            const float* s1 = &h1buf[s][grp * 8];
            const ulonglong2 va = *reinterpret_cast<const ulonglong2*>(s1);
            const ulonglong2 vb = *reinterpret_cast<const ulonglong2*>(s1 + 4);
            const float* s2 = &h2buf[grp * 8];
            const ulonglong2 vc = *reinterpret_cast<const ulonglong2*>(s2);
            const ulonglong2 vd = *reinterpret_cast<const ulonglong2*>(s2 + 4);

            ull a0 = pb2[0], a1 = pb2[1], a2 = pb2[2], a3 = pb2[3];
            {
                const ull p0 = va.x, p1 = va.y, p2 = vb.x, p3 = vb.y;
                a0 = ffma2(wi2p[0][0], p0, a0); a0 = ffma2(wi2p[0][1], p1, a0);
                a0 = ffma2(wi2p[0][2], p2, a0); a0 = ffma2(wi2p[0][3], p3, a0);
                a1 = ffma2(wi2p[1][0], p0, a1); a1 = ffma2(wi2p[1][1], p1, a1);
                a1 = ffma2(wi2p[1][2], p2, a1); a1 = ffma2(wi2p[1][3], p3, a1);
                a2 = ffma2(wi2p[2][0], p0, a2); a2 = ffma2(wi2p[2][1], p1, a2);
                a2 = ffma2(wi2p[2][2], p2, a2); a2 = ffma2(wi2p[2][3], p3, a2);
                a3 = ffma2(wi2p[3][0], p0, a3); a3 = ffma2(wi2p[3][1], p1, a3);
                a3 = ffma2(wi2p[3][2], p2, a3); a3 = ffma2(wi2p[3][3], p3, a3);
            }
            {
                const ull q0 = vc.x, q1 = vc.y, q2 = vd.x, q3 = vd.y;
                a0 = ffma2(wh2p[0][0], q0, a0); a0 = ffma2(wh2p[0][1], q1, a0);
                a0 = ffma2(wh2p[0][2], q2, a0); a0 = ffma2(wh2p[0][3], q3, a0);
                a1 = ffma2(wh2p[1][0], q0, a1); a1 = ffma2(wh2p[1][1], q1, a1);
                a1 = ffma2(wh2p[1][2], q2, a1); a1 = ffma2(wh2p[1][3], q3, a1);
                a2 = ffma2(wh2p[2][0], q0, a2); a2 = ffma2(wh2p[2][1], q1, a2);
                a2 = ffma2(wh2p[2][2], q2, a2); a2 = ffma2(wh2p[2][3], q3, a2);
                a3 = ffma2(wh2p[3][0], q0, a3); a3 = ffma2(wh2p[3][1], q1, a3);
                a3 = ffma2(wh2p[3][2], q2, a3); a3 = ffma2(wh2p[3][3], q3, a3);
            }
            bar_arrive64(3 + s);          // E[s]: h1 slot consumed (regs hold values)

            const float2 u0 = upk(a0), u1 = upk(a1), u2 = upk(a2), u3 = upk(a3);
            const float ai = sigx(u0.x + u0.y);
            const float af = sigx(u1.x + u1.y);
            const float ag = tanhx(u2.x + u2.y);
            const float ao = sigx(u3.x + u3.y);
            c2 = fmaf(af, c2, ai * ag);
            h2 = ao * tanhx(c2);
            h2buf[grp * 8 + j] = h2;      // next read ordered by next bar.sync(F)
        }

        // ---------------- epilogue: BatchNorm (eval) + MLP head ----------------
        const float scale = bn_gamma[j] * rsqrtf(bn_var[j] + 1e-5f);
        const float nrm   = fmaf(h2 - bn_mean[j], scale, bn_beta[j]);
        float p0 = w1[0 * 8 + j] * nrm;
        float p1 = w1[1 * 8 + j] * nrm;
        float p2 = w1[2 * 8 + j] * nrm;
        float p3 = w1[3 * 8 + j] * nrm;
#pragma unroll
        for (int off = 4; off > 0; off >>= 1){
            p0 += __shfl_xor_sync(FULL, p0, off);
            p1 += __shfl_xor_sync(FULL, p1, off);
            p2 += __shfl_xor_sync(FULL, p2, off);
            p3 += __shfl_xor_sync(FULL, p3, off);
        }
        if (valid && j == 0){
            float o = b2[0];
            o = fmaf(w2[0], fmaxf(p0 + b1[0], 0.f), o);
            o = fmaf(w2[1], fmaxf(p1 + b1[1], 0.f), o);
            o = fmaf(w2[2], fmaxf(p2 + b1[2], 0.f), o);
            o = fmaf(w2[3], fmaxf(p3 + b1[3], 0.f), o);
            out[e] = o;
        }
    }
}

extern "C" void kernel_launch(void* const* d_in, const int* in_sizes, int n_in,
                              void* d_out, int out_size)
{
    const float* x        = (const float*)d_in[0];
    const float* Wih1     = (const float*)d_in[1];
    const float* Whh1     = (const float*)d_in[2];
    const float* bih1     = (const float*)d_in[3];
    const float* bhh1     = (const float*)d_in[4];
    const float* Wih2     = (const float*)d_in[5];
    const float* Whh2     = (const float*)d_in[6];
    const float* bih2     = (const float*)d_in[7];
    const float* bhh2     = (const float*)d_in[8];
    const float* bn_gamma = (const float*)d_in[9];
    const float* bn_beta  = (const float*)d_in[10];
    const float* bn_mean  = (const float*)d_in[11];
    const float* bn_var   = (const float*)d_in[12];
    const float* w1       = (const float*)d_in[13];
    const float* b1       = (const float*)d_in[14];
    const float* w2       = (const float*)d_in[15];
    const float* b2       = (const float*)d_in[16];

    const int Bn = in_sizes[0] / (TSEQ * INF);
    const int grid = (Bn + 3) / 4;          // 4 elements per block (2 warps)

    lstm_forex_kernel<<<grid, 64>>>(x, Wih1, Whh1, bih1, bhh1,
                                    Wih2, Whh2, bih2, bhh2,
                                    bn_gamma, bn_beta, bn_mean, bn_var,
                                    w1, b1, w2, b2,
                                    (float*)d_out, Bn);
}

// round 7
// speedup vs baseline: 1.9387x; 1.9387x over previous
#include <cuda_runtime.h>

#define TSEQ 512
#define INF  14
#define HID  8

typedef unsigned long long ull;

__device__ __forceinline__ ull pk(float lo, float hi){
    ull r; asm("mov.b64 %0, {%1,%2};" : "=l"(r) : "f"(lo), "f"(hi)); return r;
}
__device__ __forceinline__ float2 upk(ull v){
    float2 r; asm("mov.b64 {%0,%1}, %2;" : "=f"(r.x), "=f"(r.y) : "l"(v)); return r;
}
__device__ __forceinline__ ull ffma2(ull a, ull b, ull c){
    ull d; asm("fma.rn.f32x2 %0, %1, %2, %3;" : "=l"(d) : "l"(a), "l"(b), "l"(c)); return d;
}
__device__ __forceinline__ float tanhx(float x){
    float r; asm("tanh.approx.f32 %0, %1;" : "=f"(r) : "f"(x)); return r;
}
__device__ __forceinline__ float sigx(float x){
    return fmaf(0.5f, tanhx(0.5f * x), 0.5f);
}

// 4 batch elements per warp (8 lanes each); lane owns h-index j, all 4 gate rows.
// Key structure: h1 and h2 are shuffled+packed ONCE per step right after being
// computed; the packed pairs feed L2(t) immediately and L1(t+1)/L2(t+1) next
// iteration. L2's h2-dependent partial dot is hoisted to the loop top where it
// overlaps the whole L1 chain.
__global__ __launch_bounds__(32, 1) void lstm_forex_kernel(
    const float* __restrict__ x,
    const float* __restrict__ Wih1, const float* __restrict__ Whh1,
    const float* __restrict__ bih1, const float* __restrict__ bhh1,
    const float* __restrict__ Wih2, const float* __restrict__ Whh2,
    const float* __restrict__ bih2, const float* __restrict__ bhh2,
    const float* __restrict__ bn_gamma, const float* __restrict__ bn_beta,
    const float* __restrict__ bn_mean, const float* __restrict__ bn_var,
    const float* __restrict__ w1, const float* __restrict__ b1,
    const float* __restrict__ w2, const float* __restrict__ b2,
    float* __restrict__ out, int Bn)
{
    const int lane = threadIdx.x & 31;
    const int j    = lane & 7;
    const int base = lane & 24;
    const int e    = blockIdx.x * 4 + (lane >> 3);
    const bool valid = (e < Bn);
    const int ec = valid ? e : (Bn > 0 ? Bn - 1 : 0);
    const unsigned FULL = 0xffffffffu;

    // ---- packed per-lane weights (gate rows j, j+8, j+16, j+24) ----
    ull wxp[4][7];    // (Wih1[row][2k], Wih1[row][2k+1])
    ull wh1p[4][4];   // (Whh1[row][2k], Whh1[row][2k+1])
    ull wi2p[4][4];   // (Wih2[row][2k], Wih2[row][2k+1])
    ull wh2p[4][4];   // (Whh2[row][2k], Whh2[row][2k+1])
    ull pb1[4], pb2[4];
#pragma unroll
    for (int g = 0; g < 4; g++){
        const int row = g * 8 + j;
#pragma unroll
        for (int k = 0; k < 7; k++)
            wxp[g][k] = pk(Wih1[row * 14 + 2*k], Wih1[row * 14 + 2*k + 1]);
#pragma unroll
        for (int k = 0; k < 4; k++){
            wh1p[g][k] = pk(Whh1[row * 8 + 2*k], Whh1[row * 8 + 2*k + 1]);
            wi2p[g][k] = pk(Wih2[row * 8 + 2*k], Wih2[row * 8 + 2*k + 1]);
            wh2p[g][k] = pk(Whh2[row * 8 + 2*k], Whh2[row * 8 + 2*k + 1]);
        }
        pb1[g] = pk(bih1[row] + bhh1[row], 0.f);
        pb2[g] = pk(bih2[row] + bhh2[row], 0.f);
    }

    // x[e, t, :]: 14 floats = 7 packed pairs
    const ull* px = reinterpret_cast<const ull*>(x) + (size_t)ec * (TSEQ * INF / 2);
    ull xb[7];
#pragma unroll
    for (int k = 0; k < 7; k++) xb[k] = px[k];
    px += 7;

    // packed broadcast state: h1p[k] = (h1[2k], h1[2k+1]) of my element; same for h2p
    ull h1p[4] = {0ull,0ull,0ull,0ull};
    ull h2p[4] = {0ull,0ull,0ull,0ull};
    float c1 = 0.f, c2 = 0.f, h2 = 0.f;

#pragma unroll 1
    for (int t = 0; t < TSEQ; t++){
        // ---- L2 partial: bias + Whh2·h2(t-1)  (independent of L1 chain) ----
        ull aA0 = pb2[0], aA1 = pb2[1], aA2 = pb2[2], aA3 = pb2[3];
#pragma unroll
        for (int k = 0; k < 4; k++){
            aA0 = ffma2(wh2p[0][k], h2p[k], aA0);
            aA1 = ffma2(wh2p[1][k], h2p[k], aA1);
            aA2 = ffma2(wh2p[2][k], h2p[k], aA2);
            aA3 = ffma2(wh2p[3][k], h2p[k], aA3);
        }

        // ---- L1: x-dot + recurrent dot (h1p already in registers) ----
        ull aB0 = pb1[0], aB1 = pb1[1], aB2 = pb1[2], aB3 = pb1[3];
#pragma unroll
        for (int k = 0; k < 7; k++){
            aB0 = ffma2(wxp[0][k], xb[k], aB0);
            aB1 = ffma2(wxp[1][k], xb[k], aB1);
            aB2 = ffma2(wxp[2][k], xb[k], aB2);
            aB3 = ffma2(wxp[3][k], xb[k], aB3);
        }
#pragma unroll
        for (int k = 0; k < 4; k++){
            aB0 = ffma2(wh1p[0][k], h1p[k], aB0);
            aB1 = ffma2(wh1p[1][k], h1p[k], aB1);
            aB2 = ffma2(wh1p[2][k], h1p[k], aB2);
            aB3 = ffma2(wh1p[3][k], h1p[k], aB3);
        }
        // prefetch x(t+1)
        if (t + 1 < TSEQ){
#pragma unroll
            for (int k = 0; k < 7; k++) xb[k] = px[k];
            px += 7;
        }
        // ---- L1 activations -> h1(t) ----
        float h1;
        {
            const float2 u0 = upk(aB0), u1 = upk(aB1), u2 = upk(aB2), u3 = upk(aB3);
            const float ai = sigx(u0.x + u0.y);
            const float af = sigx(u1.x + u1.y);
            const float ag = tanhx(u2.x + u2.y);
            const float ao = sigx(u3.x + u3.y);
            c1 = fmaf(af, c1, ai * ag);
            h1 = ao * tanhx(c1);
        }
        // ---- shuffle h1 ONCE; pairs feed L2(t) now and L1(t+1) next iter ----
#pragma unroll
        for (int k = 0; k < 4; k++){
            const float ha = __shfl_sync(FULL, h1, base + 2*k);
            const float hb = __shfl_sync(FULL, h1, base + 2*k + 1);
            h1p[k] = pk(ha, hb);
        }
        // ---- L2: + Wih2·h1(t), activations -> h2(t) ----
#pragma unroll
        for (int k = 0; k < 4; k++){
            aA0 = ffma2(wi2p[0][k], h1p[k], aA0);
            aA1 = ffma2(wi2p[1][k], h1p[k], aA1);
            aA2 = ffma2(wi2p[2][k], h1p[k], aA2);
            aA3 = ffma2(wi2p[3][k], h1p[k], aA3);
        }
        {
            const float2 u0 = upk(aA0), u1 = upk(aA1), u2 = upk(aA2), u3 = upk(aA3);
            const float ai = sigx(u0.x + u0.y);
            const float af = sigx(u1.x + u1.y);
            const float ag = tanhx(u2.x + u2.y);
            const float ao = sigx(u3.x + u3.y);
            c2 = fmaf(af, c2, ai * ag);
            h2 = ao * tanhx(c2);
        }
        // ---- shuffle h2 ONCE; pairs feed next iteration's L2 partial ----
        // (off the critical path: next iter starts with L1's x-dot)
#pragma unroll
        for (int k = 0; k < 4; k++){
            const float ha = __shfl_sync(FULL, h2, base + 2*k);
            const float hb = __shfl_sync(FULL, h2, base + 2*k + 1);
            h2p[k] = pk(ha, hb);
        }
    }

    // ---------------- epilogue: BatchNorm (eval) + MLP head ----------------
    const float scale = bn_gamma[j] * rsqrtf(bn_var[j] + 1e-5f);
    const float nrm   = fmaf(h2 - bn_mean[j], scale, bn_beta[j]);

    float p0 = w1[0 * 8 + j] * nrm;
    float p1 = w1[1 * 8 + j] * nrm;
    float p2 = w1[2 * 8 + j] * nrm;
    float p3 = w1[3 * 8 + j] * nrm;
#pragma unroll
    for (int off = 4; off > 0; off >>= 1){
        p0 += __shfl_xor_sync(FULL, p0, off);
        p1 += __shfl_xor_sync(FULL, p1, off);
        p2 += __shfl_xor_sync(FULL, p2, off);
        p3 += __shfl_xor_sync(FULL, p3, off);
    }
    if (valid && j == 0){
        float o = b2[0];
        o = fmaf(w2[0], fmaxf(p0 + b1[0], 0.f), o);
        o = fmaf(w2[1], fmaxf(p1 + b1[1], 0.f), o);
        o = fmaf(w2[2], fmaxf(p2 + b1[2], 0.f), o);
        o = fmaf(w2[3], fmaxf(p3 + b1[3], 0.f), o);
        out[e] = o;
    }
}

extern "C" void kernel_launch(void* const* d_in, const int* in_sizes, int n_in,
                              void* d_out, int out_size)
{
    const float* x        = (const float*)d_in[0];
    const float* Wih1     = (const float*)d_in[1];
    const float* Whh1     = (const float*)d_in[2];
    const float* bih1     = (const float*)d_in[3];
    const float* bhh1     = (const float*)d_in[4];
    const float* Wih2     = (const float*)d_in[5];
    const float* Whh2     = (const float*)d_in[6];
    const float* bih2     = (const float*)d_in[7];
    const float* bhh2     = (const float*)d_in[8];
    const float* bn_gamma = (const float*)d_in[9];
    const float* bn_beta  = (const float*)d_in[10];
    const float* bn_mean  = (const float*)d_in[11];
    const float* bn_var   = (const float*)d_in[12];
    const float* w1       = (const float*)d_in[13];
    const float* b1       = (const float*)d_in[14];
    const float* w2       = (const float*)d_in[15];
    const float* b2       = (const float*)d_in[16];

    const int Bn = in_sizes[0] / (TSEQ * INF);
    const int grid = (Bn + 3) / 4;            // 4 batch elements per warp, 1 warp/block

    lstm_forex_kernel<<<grid, 32>>>(x, Wih1, Whh1, bih1, bhh1,
                                    Wih2, Whh2, bih2, bhh2,
                                    bn_gamma, bn_beta, bn_mean, bn_var,
                                    w1, b1, w2, b2,
                                    (float*)d_out, Bn);
}